// round 4
// baseline (speedup 1.0000x reference)
#include <cuda_runtime.h>
#include <cuda_bf16.h>
#include <math.h>
#include <stdint.h>

// Spherical harmonics Re(Y_l^m), l=0..3, scipy sph_harm convention.
// Output layout: [Y0 (N*1) | Y1 (N*3) | Y2 (N*5) | Y3 (N*7)].
//
// Pipelined bulk-store version: compute slab i while cp.async.bulk drains
// slab i-1 from smem to global. Input for slab i+1 prefetched into registers.

#define C_Y00   0.28209479177387814f
#define C_Y10   0.48860251190291992f
#define C_Y11   0.34549414947133547f
#define C_Y20   0.31539156525252005f
#define C_Y21   0.77254840404659256f
#define C_Y22   0.38627420202329628f
#define C_Y30   0.37317633259011540f
#define C_Y31   0.32318018411415066f
#define C_Y32   1.02198547643328236f
#define C_Y33   0.41722382363278409f

#define THREADS   256
#define PPB       512
#define IN_F4     384                 // PPB*3/4 float4 per slab
#define BUF_FLOATS 7680               // 1536 (l1) + 2560 (l2) + 3584 (l3)
// smem: s_in 1536 + c0 512 + 2*7680 = 17408 floats = 69632 bytes
#define SMEM_BYTES (17408 * 4)

__device__ __forceinline__ uint32_t smem_u32(const void* p) {
    uint32_t a;
    asm("{ .reg .u64 t; cvta.to.shared.u64 t, %1; cvt.u32.u64 %0, t; }" : "=r"(a) : "l"(p));
    return a;
}

__device__ __forceinline__ void bulk_s2g(void* gdst, uint32_t ssrc, uint32_t bytes) {
    asm volatile("cp.async.bulk.global.shared::cta.bulk_group [%0], [%1], %2;"
                 :: "l"(gdst), "r"(ssrc), "r"(bytes) : "memory");
}

__device__ __forceinline__ void sh_compute(float x, float y, float z,
                                           float* __restrict__ s1,
                                           float* __restrict__ s2,
                                           float* __restrict__ s3, int lp) {
    float r   = sqrtf(x * x + y * y + z * z);
    float ct  = z / (r + 1e-8f);
    float ct2 = ct * ct;
    float st  = sqrtf(fmaxf(1.0f - ct2, 0.0f));
    float st2 = st * st;

    float rho2 = x * x + y * y;
    float c1, c2, c3;
    if (rho2 > 0.0f) {
        float inv_rho = rsqrtf(rho2);
        c1 = x * inv_rho;
        c2 = 2.0f * c1 * c1 - 1.0f;
        c3 = c1 * (2.0f * c2 - 1.0f);
    } else {
        c1 = 1.0f; c2 = 1.0f; c3 = 1.0f;
    }

    float y10 = C_Y10 * ct;
    float y11 = -C_Y11 * st * c1;
    s1[lp * 3 + 0] = -y11;
    s1[lp * 3 + 1] =  y10;
    s1[lp * 3 + 2] =  y11;

    float y20 = C_Y20 * (3.0f * ct2 - 1.0f);
    float y21 = -C_Y21 * ct * st * c1;
    float y22 =  C_Y22 * st2 * c2;
    s2[lp * 5 + 0] =  y22;
    s2[lp * 5 + 1] = -y21;
    s2[lp * 5 + 2] =  y20;
    s2[lp * 5 + 3] =  y21;
    s2[lp * 5 + 4] =  y22;

    float y30 =  C_Y30 * ct * (5.0f * ct2 - 3.0f);
    float y31 = -C_Y31 * (5.0f * ct2 - 1.0f) * st * c1;
    float y32 =  C_Y32 * ct * st2 * c2;
    float y33 = -C_Y33 * st * st2 * c3;
    s3[lp * 7 + 0] = -y33;
    s3[lp * 7 + 1] =  y32;
    s3[lp * 7 + 2] = -y31;
    s3[lp * 7 + 3] =  y30;
    s3[lp * 7 + 4] =  y31;
    s3[lp * 7 + 5] =  y32;
    s3[lp * 7 + 6] =  y33;
}

__global__ __launch_bounds__(THREADS)
void sh_l3_bulk_kernel(const float* __restrict__ dirs,
                       float* __restrict__ out, int n, int nslab) {
    extern __shared__ float smem[];
    float* s_in = smem;                 // 1536 floats
    float* s_c0 = smem + 1536;          // 512 floats (constant Y00)
    float* bufs = smem + 2048;          // 2 x 7680 floats

    const int tid = threadIdx.x;
    const int G = gridDim.x;

    // init constant l=0 staging buffer once
    for (int j = tid; j < PPB; j += THREADS) s_c0[j] = C_Y00;

    const float4* in4 = (const float4*)dirs;
    const long long total4 = ((long long)n * 3) >> 2;
    const long long nll = n;

    int slab = blockIdx.x;

    // preload input for first slab into registers
    float4 r0, r1;
    r0 = make_float4(0.f, 0.f, 0.f, 0.f);
    r1 = r0;
    {
        long long b4 = (long long)slab * IN_F4;
        if (b4 + tid < total4)            r0 = in4[b4 + tid];
        if (tid + THREADS < IN_F4 && b4 + tid + THREADS < total4)
                                          r1 = in4[b4 + tid + THREADS];
    }

    int it = 0;
    for (; slab < nslab; slab += G, it++) {
        const long long base_pt = (long long)slab * PPB;
        const bool full = (base_pt + PPB <= nll);

        // stage current input into smem
        ((float4*)s_in)[tid] = r0;
        if (tid + THREADS < IN_F4) ((float4*)s_in)[tid + THREADS] = r1;

        // prefetch next slab's input
        {
            long long ns = (long long)slab + G;
            if (ns < nslab) {
                long long b4 = ns * IN_F4;
                if (b4 + tid < total4)            r0 = in4[b4 + tid];
                if (tid + THREADS < IN_F4 && b4 + tid + THREADS < total4)
                                                  r1 = in4[b4 + tid + THREADS];
            }
        }

        float* buf = bufs + (it & 1) * BUF_FLOATS;
        float* s1 = buf;
        float* s2 = buf + 1536;
        float* s3 = buf + 4096;

        // ensure the bulk-store group that last read this buffer has drained
        if (tid == 0)
            asm volatile("cp.async.bulk.wait_group.read 1;" ::: "memory");
        __syncthreads();   // S1: s_in visible, buffer free

        if (full) {
            #pragma unroll
            for (int p = 0; p < 2; p++) {
                int lp = tid + p * THREADS;
                sh_compute(s_in[lp * 3 + 0], s_in[lp * 3 + 1], s_in[lp * 3 + 2],
                           s1, s2, s3, lp);
            }
            __syncthreads();   // S2: scatter complete
            if (tid == 0) {
                asm volatile("fence.proxy.async.shared::cta;" ::: "memory");
                bulk_s2g(out + base_pt,                smem_u32(s_c0), PPB * 4);
                bulk_s2g(out + nll + base_pt * 3,      smem_u32(s1),   PPB * 12);
                bulk_s2g(out + 4 * nll + base_pt * 5,  smem_u32(s2),   PPB * 20);
                bulk_s2g(out + 9 * nll + base_pt * 7,  smem_u32(s3),   PPB * 28);
                asm volatile("cp.async.bulk.commit_group;" ::: "memory");
            }
        } else {
            // partial tail slab: direct scalar path
            #pragma unroll
            for (int p = 0; p < 2; p++) {
                long long gp = base_pt + tid + p * THREADS;
                if (gp < nll) {
                    float x = dirs[3 * gp + 0];
                    float y = dirs[3 * gp + 1];
                    float z = dirs[3 * gp + 2];
                    float tmp1[3 * PPB], *d1 = tmp1;  (void)d1; // not used
                    // compute directly and scatter to global
                    float r   = sqrtf(x * x + y * y + z * z);
                    float ct  = z / (r + 1e-8f);
                    float ct2 = ct * ct;
                    float st  = sqrtf(fmaxf(1.0f - ct2, 0.0f));
                    float st2 = st * st;
                    float rho2 = x * x + y * y;
                    float c1, c2, c3;
                    if (rho2 > 0.0f) {
                        float inv_rho = rsqrtf(rho2);
                        c1 = x * inv_rho;
                        c2 = 2.0f * c1 * c1 - 1.0f;
                        c3 = c1 * (2.0f * c2 - 1.0f);
                    } else { c1 = 1.0f; c2 = 1.0f; c3 = 1.0f; }

                    out[gp] = C_Y00;
                    float y10 = C_Y10 * ct, y11 = -C_Y11 * st * c1;
                    float* o1 = out + nll;
                    o1[3 * gp + 0] = -y11; o1[3 * gp + 1] = y10; o1[3 * gp + 2] = y11;
                    float y20 = C_Y20 * (3.0f * ct2 - 1.0f);
                    float y21 = -C_Y21 * ct * st * c1;
                    float y22 =  C_Y22 * st2 * c2;
                    float* o2 = out + 4 * nll;
                    o2[5 * gp + 0] = y22; o2[5 * gp + 1] = -y21; o2[5 * gp + 2] = y20;
                    o2[5 * gp + 3] = y21; o2[5 * gp + 4] = y22;
                    float y30 =  C_Y30 * ct * (5.0f * ct2 - 3.0f);
                    float y31 = -C_Y31 * (5.0f * ct2 - 1.0f) * st * c1;
                    float y32 =  C_Y32 * ct * st2 * c2;
                    float y33 = -C_Y33 * st * st2 * c3;
                    float* o3 = out + 9 * nll;
                    o3[7 * gp + 0] = -y33; o3[7 * gp + 1] = y32; o3[7 * gp + 2] = -y31;
                    o3[7 * gp + 3] = y30;  o3[7 * gp + 4] = y31; o3[7 * gp + 5] = y32;
                    o3[7 * gp + 6] = y33;
                }
            }
            __syncthreads();
            if (tid == 0)
                asm volatile("cp.async.bulk.commit_group;" ::: "memory");
        }
    }

    // drain all outstanding bulk stores before smem is released
    if (tid == 0)
        asm volatile("cp.async.bulk.wait_group.read 0;" ::: "memory");
    __syncthreads();
}

// Fallback for n % 4 != 0 (bulk dst alignment requires 16B-aligned region bases)
__global__ void sh_l3_naive_kernel(const float* __restrict__ dirs,
                                   float* __restrict__ out, int n) {
    int i = blockIdx.x * blockDim.x + threadIdx.x;
    if (i >= n) return;
    float x = dirs[3 * i], y = dirs[3 * i + 1], z = dirs[3 * i + 2];
    float r = sqrtf(x * x + y * y + z * z);
    float ct = z / (r + 1e-8f), ct2 = ct * ct;
    float st = sqrtf(fmaxf(1.0f - ct2, 0.0f)), st2 = st * st;
    float rho2 = x * x + y * y, c1, c2, c3;
    if (rho2 > 0.0f) {
        float ir = rsqrtf(rho2);
        c1 = x * ir; c2 = 2.0f * c1 * c1 - 1.0f; c3 = c1 * (2.0f * c2 - 1.0f);
    } else { c1 = c2 = c3 = 1.0f; }
    out[i] = C_Y00;
    float y10 = C_Y10 * ct, y11 = -C_Y11 * st * c1;
    float* o1 = out + (size_t)n;
    o1[3 * i] = -y11; o1[3 * i + 1] = y10; o1[3 * i + 2] = y11;
    float y20 = C_Y20 * (3.0f * ct2 - 1.0f), y21 = -C_Y21 * ct * st * c1,
          y22 = C_Y22 * st2 * c2;
    float* o2 = out + (size_t)4 * n;
    o2[5 * i] = y22; o2[5 * i + 1] = -y21; o2[5 * i + 2] = y20;
    o2[5 * i + 3] = y21; o2[5 * i + 4] = y22;
    float y30 = C_Y30 * ct * (5.0f * ct2 - 3.0f),
          y31 = -C_Y31 * (5.0f * ct2 - 1.0f) * st * c1,
          y32 = C_Y32 * ct * st2 * c2, y33 = -C_Y33 * st * st2 * c3;
    float* o3 = out + (size_t)9 * n;
    o3[7 * i] = -y33; o3[7 * i + 1] = y32; o3[7 * i + 2] = -y31;
    o3[7 * i + 3] = y30; o3[7 * i + 4] = y31; o3[7 * i + 5] = y32;
    o3[7 * i + 6] = y33;
}

extern "C" void kernel_launch(void* const* d_in, const int* in_sizes, int n_in,
                              void* d_out, int out_size) {
    const float* dirs = (const float*)d_in[0];
    float* out = (float*)d_out;
    int n = in_sizes[0] / 3;

    if ((n & 3) != 0) {
        int blocks = (n + 255) / 256;
        sh_l3_naive_kernel<<<blocks, 256>>>(dirs, out, n);
        return;
    }

    int nslab = (n + PPB - 1) / PPB;
    int G = nslab < 444 ? nslab : 444;

    static int smem_set = 0;
    if (!smem_set) {
        cudaFuncSetAttribute(sh_l3_bulk_kernel,
                             cudaFuncAttributeMaxDynamicSharedMemorySize, SMEM_BYTES);
        smem_set = 1;
    }
    sh_l3_bulk_kernel<<<G, THREADS, SMEM_BYTES>>>(dirs, out, n, nslab);
}

// round 5
// speedup vs baseline: 1.1578x; 1.1578x over previous
#include <cuda_runtime.h>
#include <cuda_bf16.h>
#include <math.h>

// Spherical harmonics Re(Y_l^m), l=0..3, scipy sph_harm convention.
// Output layout: [Y0 (N*1) | Y1 (N*3) | Y2 (N*5) | Y3 (N*7)].
//
// smem-staged, fully coalesced float4 I/O with streaming cache hints.
// 256 threads x 2 points = 512-point slab per block.

#define C_Y00   0.28209479177387814f
#define C_Y10   0.48860251190291992f
#define C_Y11   0.34549414947133547f
#define C_Y20   0.31539156525252005f
#define C_Y21   0.77254840404659256f
#define C_Y22   0.38627420202329628f
#define C_Y30   0.37317633259011540f
#define C_Y31   0.32318018411415066f
#define C_Y32   1.02198547643328236f
#define C_Y33   0.41722382363278409f

#define THREADS 256
#define PPT     2
#define PPB     (THREADS * PPT)   // 512

__global__ __launch_bounds__(THREADS)
void sh_l3_staged_kernel(const float* __restrict__ dirs,
                         float* __restrict__ out, int n) {
    __shared__ float s_in[PPB * 3];   // 6 KB
    __shared__ float s1[PPB * 3];     // 6 KB
    __shared__ float s2[PPB * 5];     // 10 KB
    __shared__ float s3[PPB * 7];     // 14 KB  -> 36 KB total

    const int tid = threadIdx.x;
    const long long base_pt = (long long)blockIdx.x * PPB;
    const long long nll = n;

    // ---- Phase 0: coalesced float4 streaming load of input slab ----
    {
        const float4* in4 = (const float4*)dirs;
        const long long total4 = (nll * 3) >> 2;
        const long long base4 = base_pt * 3 / 4;    // PPB*3 = 1536, div by 4
        #pragma unroll
        for (int k = 0; k < (PPB * 3) / 4 / THREADS; k++) {   // 384/256 -> handled below
            ;
        }
        // 384 float4 per slab, 256 threads: 2 strided passes with guard
        #pragma unroll
        for (int k = 0; k < 2; k++) {
            int j = tid + k * THREADS;
            if (j < (PPB * 3) / 4) {
                long long g4 = base4 + j;
                if (g4 < total4) ((float4*)s_in)[j] = __ldg(&in4[g4]);
            }
        }
    }
    __syncthreads();

    // ---- Phase 1: compute, scatter to smem (odd strides: conflict-free) ----
    #pragma unroll
    for (int p = 0; p < PPT; p++) {
        const int lp = tid + p * THREADS;
        const long long gp = base_pt + lp;
        if (gp >= nll) break;

        float x = s_in[lp * 3 + 0];
        float y = s_in[lp * 3 + 1];
        float z = s_in[lp * 3 + 2];

        float r   = sqrtf(x * x + y * y + z * z);
        float ct  = z / (r + 1e-8f);
        float ct2 = ct * ct;
        float st  = sqrtf(fmaxf(1.0f - ct2, 0.0f));
        float st2 = st * st;

        float rho2 = x * x + y * y;
        float c1, c2, c3;
        if (rho2 > 0.0f) {
            float inv_rho = rsqrtf(rho2);
            c1 = x * inv_rho;
            c2 = 2.0f * c1 * c1 - 1.0f;
            c3 = c1 * (2.0f * c2 - 1.0f);
        } else {
            c1 = 1.0f; c2 = 1.0f; c3 = 1.0f;
        }

        float y10 = C_Y10 * ct;
        float y11 = -C_Y11 * st * c1;
        s1[lp * 3 + 0] = -y11;
        s1[lp * 3 + 1] =  y10;
        s1[lp * 3 + 2] =  y11;

        float y20 = C_Y20 * (3.0f * ct2 - 1.0f);
        float y21 = -C_Y21 * ct * st * c1;
        float y22 =  C_Y22 * st2 * c2;
        s2[lp * 5 + 0] =  y22;
        s2[lp * 5 + 1] = -y21;
        s2[lp * 5 + 2] =  y20;
        s2[lp * 5 + 3] =  y21;
        s2[lp * 5 + 4] =  y22;

        float y30 =  C_Y30 * ct * (5.0f * ct2 - 3.0f);
        float y31 = -C_Y31 * (5.0f * ct2 - 1.0f) * st * c1;
        float y32 =  C_Y32 * ct * st2 * c2;
        float y33 = -C_Y33 * st * st2 * c3;
        s3[lp * 7 + 0] = -y33;
        s3[lp * 7 + 1] =  y32;
        s3[lp * 7 + 2] = -y31;
        s3[lp * 7 + 3] =  y30;
        s3[lp * 7 + 4] =  y31;
        s3[lp * 7 + 5] =  y32;
        s3[lp * 7 + 6] =  y33;
    }
    __syncthreads();

    // ---- Phase 2: coalesced float4 streaming flush ----
    // l = 0: pure constant, no staging needed. 128 float4 per block.
    if (tid < PPB / 4) {
        long long fbase = base_pt;
        long long rem = nll - fbase;
        long long idx = (long long)tid * 4;
        float4 v = make_float4(C_Y00, C_Y00, C_Y00, C_Y00);
        if (idx + 4 <= rem) {
            __stcs((float4*)(out + fbase + idx), v);
        } else {
            for (int e = 0; e < 4; e++)
                if (idx + e < rem) out[fbase + idx + e] = C_Y00;
        }
    }

    // l = 1: 384 float4
    {
        float* gbase = out + nll;
        long long fbase = base_pt * 3;
        long long rem = nll * 3 - fbase;
        #pragma unroll
        for (int k = 0; k < 2; k++) {
            int j = tid + k * THREADS;
            if (j < (PPB * 3) / 4) {
                long long idx = (long long)j * 4;
                if (idx + 4 <= rem) {
                    __stcs((float4*)(gbase + fbase + idx), ((const float4*)s1)[j]);
                } else {
                    for (int e = 0; e < 4; e++)
                        if (idx + e < rem) gbase[fbase + idx + e] = s1[idx + e];
                }
            }
        }
    }

    // l = 2: 640 float4
    {
        float* gbase = out + 4 * nll;
        long long fbase = base_pt * 5;
        long long rem = nll * 5 - fbase;
        #pragma unroll
        for (int k = 0; k < 3; k++) {
            int j = tid + k * THREADS;
            if (j < (PPB * 5) / 4) {
                long long idx = (long long)j * 4;
                if (idx + 4 <= rem) {
                    __stcs((float4*)(gbase + fbase + idx), ((const float4*)s2)[j]);
                } else {
                    for (int e = 0; e < 4; e++)
                        if (idx + e < rem) gbase[fbase + idx + e] = s2[idx + e];
                }
            }
        }
    }

    // l = 3: 896 float4
    {
        float* gbase = out + 9 * nll;
        long long fbase = base_pt * 7;
        long long rem = nll * 7 - fbase;
        #pragma unroll
        for (int k = 0; k < 4; k++) {
            int j = tid + k * THREADS;
            if (j < (PPB * 7) / 4) {
                long long idx = (long long)j * 4;
                if (idx + 4 <= rem) {
                    __stcs((float4*)(gbase + fbase + idx), ((const float4*)s3)[j]);
                } else {
                    for (int e = 0; e < 4; e++)
                        if (idx + e < rem) gbase[fbase + idx + e] = s3[idx + e];
                }
            }
        }
    }
}

extern "C" void kernel_launch(void* const* d_in, const int* in_sizes, int n_in,
                              void* d_out, int out_size) {
    const float* dirs = (const float*)d_in[0];
    float* out = (float*)d_out;
    int n = in_sizes[0] / 3;

    int blocks = (n + PPB - 1) / PPB;
    sh_l3_staged_kernel<<<blocks, THREADS>>>(dirs, out, n);
}